// round 2
// baseline (speedup 1.0000x reference)
#include <cuda_runtime.h>

// ---------------------------------------------------------------------------
// SSIM loss, fully fused:
//   per 32x32 tile: load pred/target halo tile -> horizontal 11-tap Gaussian
//   blur of {p, t, p^2, t^2, p*t} -> vertical 11-tap blur -> SSIM map
//   -> block partial sum -> atomicAdd(double)
//   init kernel zeroes the accumulator, finalize writes 1 - sum/N.
// Gaussian weights are function-local constexpr so ptxas emits FFMA-imm.
// ---------------------------------------------------------------------------

#define TILE 32
#define IN   42          // TILE + 10 halo
#define SP   43          // smem stride for input tiles (odd -> conflict-free)
#define SH   33          // smem stride for h arrays

// 1D Gaussian, K=11, sigma=1.5, normalized (sum = 1)
#define GW_INIT { \
    0.00102840f, 0.00759879f, 0.03600075f, 0.10936067f, 0.21300550f, \
    0.26601167f, \
    0.21300550f, 0.10936067f, 0.03600075f, 0.00759879f, 0.00102840f }

__device__ double g_ssim_sum;

__global__ void ssim_init_kernel() { g_ssim_sum = 0.0; }

__global__ void ssim_final_kernel(float* out, float inv_n) {
    out[0] = 1.0f - (float)(g_ssim_sum) * inv_n;
}

__global__ __launch_bounds__(256) void ssim_main_kernel(
    const float* __restrict__ pred, const float* __restrict__ tgt)
{
    constexpr float GW[11] = GW_INIT;

    __shared__ float s_p[IN][SP];
    __shared__ float s_t[IN][SP];
    __shared__ float s_h[5][IN][SH];
    __shared__ float s_wsum[8];

    const int tid = threadIdx.x;
    const int gx0 = blockIdx.x * TILE - 5;
    const int gy0 = blockIdx.y * TILE - 5;
    const size_t plane_off = (size_t)blockIdx.z * (512 * 512);
    const float* pbase = pred + plane_off;
    const float* tbase = tgt  + plane_off;

    // ---- load halo'd input tiles (zero pad outside image) ----
    #pragma unroll
    for (int idx = tid; idx < IN * IN; idx += 256) {
        int r = idx / IN;
        int c = idx - r * IN;
        int gy = gy0 + r;
        int gx = gx0 + c;
        float pv = 0.0f, tv = 0.0f;
        if ((unsigned)gy < 512u && (unsigned)gx < 512u) {
            int g = gy * 512 + gx;
            pv = __ldg(pbase + g);
            tv = __ldg(tbase + g);
        }
        s_p[r][c] = pv;
        s_t[r][c] = tv;
    }
    __syncthreads();

    // ---- horizontal separable pass: 42 rows x 4 spans of 8 cols = 168 items ----
    if (tid < 168) {
        const int r  = tid >> 2;
        const int c0 = (tid & 3) * 8;
        float hp[8], ht[8], hpp[8], htt[8], hpt[8];
        #pragma unroll
        for (int j = 0; j < 8; j++) { hp[j]=0.f; ht[j]=0.f; hpp[j]=0.f; htt[j]=0.f; hpt[j]=0.f; }

        #pragma unroll
        for (int k = 0; k < 18; k++) {
            float p = s_p[r][c0 + k];
            float t = s_t[r][c0 + k];
            float pp = p * p;
            float tt = t * t;
            float pt = p * t;
            #pragma unroll
            for (int j = 0; j < 8; j++) {
                const int w = k - j;
                if (w >= 0 && w < 11) {
                    hp[j]  = fmaf(GW[w], p,  hp[j]);
                    ht[j]  = fmaf(GW[w], t,  ht[j]);
                    hpp[j] = fmaf(GW[w], pp, hpp[j]);
                    htt[j] = fmaf(GW[w], tt, htt[j]);
                    hpt[j] = fmaf(GW[w], pt, hpt[j]);
                }
            }
        }
        #pragma unroll
        for (int j = 0; j < 8; j++) {
            s_h[0][r][c0 + j] = hp[j];
            s_h[1][r][c0 + j] = ht[j];
            s_h[2][r][c0 + j] = hpp[j];
            s_h[3][r][c0 + j] = htt[j];
            s_h[4][r][c0 + j] = hpt[j];
        }
    }
    __syncthreads();

    // ---- vertical pass: each thread does 4 consecutive output rows, one col ----
    const int col  = tid & 31;
    const int row0 = (tid >> 5) * 4;

    float vp[4], vt[4], vpp[4], vtt[4], vpt[4];
    #pragma unroll
    for (int o = 0; o < 4; o++) { vp[o]=0.f; vt[o]=0.f; vpp[o]=0.f; vtt[o]=0.f; vpt[o]=0.f; }

    #pragma unroll
    for (int i = 0; i < 14; i++) {
        float a0 = s_h[0][row0 + i][col];
        float a1 = s_h[1][row0 + i][col];
        float a2 = s_h[2][row0 + i][col];
        float a3 = s_h[3][row0 + i][col];
        float a4 = s_h[4][row0 + i][col];
        #pragma unroll
        for (int o = 0; o < 4; o++) {
            const int w = i - o;
            if (w >= 0 && w < 11) {
                vp[o]  = fmaf(GW[w], a0, vp[o]);
                vt[o]  = fmaf(GW[w], a1, vt[o]);
                vpp[o] = fmaf(GW[w], a2, vpp[o]);
                vtt[o] = fmaf(GW[w], a3, vtt[o]);
                vpt[o] = fmaf(GW[w], a4, vpt[o]);
            }
        }
    }

    // ---- SSIM map + local sum ----
    float local = 0.0f;
    #pragma unroll
    for (int o = 0; o < 4; o++) {
        float mp  = vp[o];
        float mt  = vt[o];
        float mpp = mp * mp;
        float mtt = mt * mt;
        float mpt = mp * mt;
        float sp  = fmaxf(vpp[o] - mpp, 0.0f);
        float st  = fmaxf(vtt[o] - mtt, 0.0f);
        float spt = vpt[o] - mpt;
        float num = fmaf(2.0f, mpt, 1e-4f) * fmaf(2.0f, spt, 9e-4f);
        float den = (mpp + mtt + 1e-4f) * (sp + st + 9e-4f);
        local += __fdividef(num, den);
    }

    // ---- reduction: warp shuffle -> smem -> one double atomic per block ----
    #pragma unroll
    for (int off = 16; off; off >>= 1)
        local += __shfl_xor_sync(0xffffffffu, local, off);
    if ((tid & 31) == 0) s_wsum[tid >> 5] = local;
    __syncthreads();
    if (tid == 0) {
        float bs = 0.0f;
        #pragma unroll
        for (int i = 0; i < 8; i++) bs += s_wsum[i];
        atomicAdd(&g_ssim_sum, (double)bs);
    }
}

extern "C" void kernel_launch(void* const* d_in, const int* in_sizes, int n_in,
                              void* d_out, int out_size)
{
    const float* pred = (const float*)d_in[0];
    const float* tgt  = (const float*)d_in[1];
    float* out = (float*)d_out;

    const int n_elems = in_sizes[0];            // B*C*H*W
    const int planes  = n_elems / (512 * 512);  // B*C

    ssim_init_kernel<<<1, 1>>>();
    dim3 grid(512 / TILE, 512 / TILE, planes);
    ssim_main_kernel<<<grid, 256>>>(pred, tgt);
    ssim_final_kernel<<<1, 1>>>(out, 1.0f / (float)n_elems);
}